// round 14
// baseline (speedup 1.0000x reference)
#include <cuda_runtime.h>
#include <cuda_fp16.h>
#include <math.h>
#include <stdint.h>

#define NB 512
#define NT 256
#define NC 384
#define NH 64
#define NS 256
#define NM (NB*NT)   // 131072 rows

// scratch (device globals: allocation-guard safe)
__device__ __align__(16) __half g_xh[NM * NC];    // x fp16 [row][384] (written by vproj)
__device__ __align__(16) __half g_v[NM * 64];     // v fp16 [row][64]
__device__ __align__(16) __half g_wv[64 * 384];   // Wv [n][k] K-major fp16
__device__ __align__(16) __half g_wu[384 * 256];  // Wu = Wq@Wql + Wk@Wkl, [k][s] fp16

// ---------------- mma.sync / cp.async helpers (baseline PTX ISA) ----------------
#define LDSM_X4(r, addr)                                                        \
    asm volatile("ldmatrix.sync.aligned.m8n8.x4.shared.b16 {%0,%1,%2,%3}, [%4];" \
        : "=r"((r)[0]), "=r"((r)[1]), "=r"((r)[2]), "=r"((r)[3]) : "r"(addr))

#define LDSM_X4_T(r, addr)                                                      \
    asm volatile("ldmatrix.sync.aligned.m8n8.x4.trans.shared.b16 {%0,%1,%2,%3}, [%4];" \
        : "=r"((r)[0]), "=r"((r)[1]), "=r"((r)[2]), "=r"((r)[3]) : "r"(addr))

#define MMA_F16(d, a, b)                                                        \
    asm volatile("mma.sync.aligned.m16n8k16.row.col.f32.f16.f16.f32 "           \
        "{%0,%1,%2,%3}, {%4,%5,%6,%7}, {%8,%9}, {%0,%1,%2,%3};"                 \
        : "+f"((d)[0]), "+f"((d)[1]), "+f"((d)[2]), "+f"((d)[3])                \
        : "r"((a)[0]), "r"((a)[1]), "r"((a)[2]), "r"((a)[3]),                   \
          "r"((b)[0]), "r"((b)[1]))

#define CP_ASYNC16(dst, src)                                                    \
    asm volatile("cp.async.cg.shared.global [%0], [%1], 16;"                    \
        :: "r"(dst), "l"(src))
#define CP_COMMIT  asm volatile("cp.async.commit_group;" ::: "memory")
#define CP_WAIT0   asm volatile("cp.async.wait_group 0;" ::: "memory")
#define CP_WAIT1   asm volatile("cp.async.wait_group 1;" ::: "memory")

static __device__ __forceinline__ uint32_t pack_h2(float a, float b) {
    __half2 t = __floats2half2_rn(a, b);
    return *(uint32_t*)&t;
}
static __device__ __forceinline__ uint32_t smaddr(const void* p) {
    return (uint32_t)__cvta_generic_to_shared(p);
}
static __device__ __forceinline__ float tanh_fast(float v) {
    float y;
    asm("tanh.approx.f32 %0, %1;" : "=f"(y) : "f"(v));
    return y;
}

// ---------------- prep: Wu = Wq@Wql + Wk@Wkl (8 c-rows/block, LDG reuse) + Wv->fp16 ----------------
__global__ __launch_bounds__(256) void prep_kernel(
    const float* __restrict__ Wq, const float* __restrict__ Wk,
    const float* __restrict__ Wql, const float* __restrict__ Wkl,
    const float* __restrict__ Wv)
{
    __shared__ float qr_[8][64], kr_[8][64];
    const int bb = blockIdx.x;
    const int s  = threadIdx.x;
    if (bb < 48) {
        const int c0 = bb * 8;
        for (int L = s; L < 512; L += 256) {
            int cc = L >> 6, h = L & 63;
            qr_[cc][h] = Wq[(c0 + cc) * 64 + h];
            kr_[cc][h] = Wk[(c0 + cc) * 64 + h];
        }
        __syncthreads();
        float acc[8];
#pragma unroll
        for (int cc = 0; cc < 8; cc++) acc[cc] = 0.f;
#pragma unroll 4
        for (int h = 0; h < 64; h++) {
            float wql = Wql[h * 256 + s];
            float wkl = Wkl[h * 256 + s];
#pragma unroll
            for (int cc = 0; cc < 8; cc++)
                acc[cc] = fmaf(qr_[cc][h], wql, fmaf(kr_[cc][h], wkl, acc[cc]));
        }
#pragma unroll
        for (int cc = 0; cc < 8; cc++)
            g_wu[(c0 + cc) * 256 + s] = __float2half_rn(acc[cc]);
    } else {
        const int idx = (bb - 48) * 256 + s;
        if (idx < 64 * 384) {
            const int n = idx / 384, k = idx % 384;
            g_wv[idx] = __float2half_rn(Wv[k * 64 + n]);
        }
    }
}

// ---------------- Kernel A: v projection + x fp16 export (unchanged from R13) ----------------
#define VPROJ_SMEM ((64*392 + 256*40) * 2)   // 70656 B

__global__ __launch_bounds__(256, 2) void vproj_kernel(const float* __restrict__ x)
{
    extern __shared__ __half smv[];
    __half* sWv = smv;               // [64][392]
    __half* sX  = smv + 64 * 392;    // [256][40]

    const int tid  = threadIdx.x;
    const int lane = tid & 31;
    const int w    = tid >> 5;
    const int wm   = w & 3;
    const int wn   = w >> 2;
    const int m0   = blockIdx.x * 256;

    const int a_row = (lane & 7) + ((lane >> 3) & 1) * 8;
    const int a_col = (lane >> 4) * 8;
    const int b_row = ((lane >> 4) * 8) + (lane & 7);
    const int b_k8  = ((lane >> 3) & 1) * 8;
    const int qr    = lane >> 2;
    const int qc    = (lane & 3) * 2;

    for (int L = tid; L < 3072; L += 256) {
        int n = L / 48, seg = L % 48;
        CP_ASYNC16(smaddr(&sWv[n * 392 + seg * 8]), &g_wv[(size_t)n * NC + seg * 8]);
    }
    CP_COMMIT;

    const int xrow = tid >> 3, xseg = tid & 7;
    float4 vv[8];
    auto ldgX = [&](int c) {
#pragma unroll
        for (int i = 0; i < 8; i++) {
            int row = xrow + 32 * i;
            vv[i] = *(const float4*)&x[(size_t)(m0 + row) * NC + c * 32 + xseg * 4];
        }
    };
    auto cvtX = [&](int c) {
#pragma unroll
        for (int i = 0; i < 8; i++) {
            int row = xrow + 32 * i;
            __half h[4];
            h[0] = __float2half_rn(vv[i].x); h[1] = __float2half_rn(vv[i].y);
            h[2] = __float2half_rn(vv[i].z); h[3] = __float2half_rn(vv[i].w);
            *(uint2*)&sX[row * 40 + xseg * 4] = *(uint2*)h;
            *(uint2*)&g_xh[(size_t)(m0 + row) * NC + c * 32 + xseg * 4] = *(uint2*)h;
        }
    };

    ldgX(0);
    CP_WAIT0;
    cvtX(0);
    __syncthreads();

    float acc[4][4][4];
#pragma unroll
    for (int mi = 0; mi < 4; mi++)
#pragma unroll
        for (int ni = 0; ni < 4; ni++)
#pragma unroll
            for (int q = 0; q < 4; q++) acc[mi][ni][q] = 0.f;

    for (int c = 0; c < 12; c++) {
        if (c < 11) ldgX(c + 1);
#pragma unroll
        for (int kk = 0; kk < 2; kk++) {
            const int kglob = c * 32 + kk * 16;
            uint32_t ah[4][4];
#pragma unroll
            for (int mi = 0; mi < 4; mi++)
                LDSM_X4(ah[mi], smaddr(&sX[(wm * 64 + mi * 16 + a_row) * 40 + kk * 16 + a_col]));
#pragma unroll
            for (int ni = 0; ni < 4; ni += 2) {
                uint32_t bh[4];
                LDSM_X4(bh, smaddr(&sWv[(wn * 32 + ni * 8 + b_row) * 392 + kglob + b_k8]));
#pragma unroll
                for (int mi = 0; mi < 4; mi++) {
                    MMA_F16(acc[mi][ni],     ah[mi], bh);
                    MMA_F16(acc[mi][ni + 1], ah[mi], bh + 2);
                }
            }
        }
        __syncthreads();
        if (c < 11) cvtX(c + 1);
        __syncthreads();
    }

#pragma unroll
    for (int mi = 0; mi < 4; mi++) {
        int r0 = m0 + wm * 64 + mi * 16 + qr;
#pragma unroll
        for (int ni = 0; ni < 4; ni++) {
            int col = wn * 32 + ni * 8 + qc;
            *(uint32_t*)&g_v[(size_t)r0 * 64 + col]       = pack_h2(acc[mi][ni][0], acc[mi][ni][1]);
            *(uint32_t*)&g_v[(size_t)(r0 + 8) * 64 + col] = pack_h2(acc[mi][ni][2], acc[mi][ni][3]);
        }
    }
}

// ---------------- Kernel B: fused u-GEMM + softmax + p@v (x fully smem-resident) ----------------
// sX [64][392] = 50176 B resident; W 3-stage [3][32][SLIMP]; rowsum at tail.
#define ATTN_SMEM_BYTES 101376

template <int SLIM>
__device__ __forceinline__ void attn_body(float* __restrict__ out, int b, int tb)
{
    constexpr int SLIMP = SLIM + 8;
    constexpr int NTW   = SLIM / 16;
    constexpr int KW    = SLIM / 2;

    extern __shared__ char smraw[];
    // phase 1
    __half* sX  = (__half*)smraw;             // [64][392]   (resident x)
    __half* sWH = sX + 64 * 392;              // [3][32][SLIMP]
    // phase 2 (overlays sX region)
    __half* sV  = (__half*)smraw;             // [SLIM][72]  <= 36864 B
    float* sOutA   = (float*)smraw;           // [64][72]
    float* sOutB   = sOutA + 64 * 72;
    float* rowsumS = (float*)(smraw + 100864);// [2][64]

    const int tid  = threadIdx.x;
    const int lane = tid & 31;
    const int w    = tid >> 5;
    const int wm   = w >> 1;
    const int wn   = w & 1;

    const int a_row  = (lane & 7) + ((lane >> 3) & 1) * 8;
    const int a_col  = (lane >> 4) * 8;
    const int kt_off = (lane & 7) | (((lane >> 3) & 1) << 3);
    const int nt_off = (lane >> 4) * 8;
    const int qr     = lane >> 2;
    const int qc     = (lane & 3) * 2;
    const int base_row = b * NT + tb * 64;

    const int limit = tb * 64 + wm * 16 + 15;
    const int nw0   = wn * KW;

    auto stageW = [&](int c, int buf) {
        const int kc = c * 32;
        for (int L = tid; L < 4 * SLIM; L += 256) {
            int r = L / (SLIM / 8), cs = L % (SLIM / 8);
            CP_ASYNC16(smaddr(&sWH[(buf * 32 + r) * SLIMP + cs * 8]),
                       &g_wu[(size_t)(kc + r) * 256 + cs * 8]);
        }
    };

    // prologue: resident x (group 0), W stages 0,1 (groups 1,2)
    for (int L = tid; L < 3072; L += 256) {   // 64 rows x 48 segs
        int row = L / 48, seg = L % 48;
        CP_ASYNC16(smaddr(&sX[row * 392 + seg * 8]),
                   &g_xh[(size_t)(base_row + row) * NC + seg * 8]);
    }
    CP_COMMIT;
    stageW(0, 0); CP_COMMIT;
    stageW(1, 1); CP_COMMIT;

    // ---- GEMM1: u = x @ Wu, K=384, 12 chunks, 3-stage W pipeline ----
    float acc[NTW][4];
#pragma unroll
    for (int j = 0; j < NTW; j++)
#pragma unroll
        for (int q = 0; q < 4; q++) acc[j][q] = 0.f;

    for (int c = 0; c < 12; c++) {
        if (c == 11) { CP_WAIT0; } else { CP_WAIT1; }
        __syncthreads();
        if (c + 2 < 12) { stageW(c + 2, (c + 2) % 3); CP_COMMIT; }
        const int buf = c % 3;
#pragma unroll
        for (int kk = 0; kk < 2; kk++) {
            uint32_t ah[4];
            LDSM_X4(ah, smaddr(&sX[(wm * 16 + a_row) * 392 + c * 32 + kk * 16 + a_col]));
#pragma unroll
            for (int j = 0; j < NTW; j += 2) {
                const int n0 = nw0 + j * 8;
                if (n0 <= limit) {   // warp-uniform causal tile-pair skip
                    uint32_t bh[4];
                    LDSM_X4_T(bh, smaddr(&sWH[(buf * 32 + kk * 16 + kt_off) * SLIMP + n0 + nt_off]));
                    MMA_F16(acc[j],     ah, bh);
                    MMA_F16(acc[j + 1], ah, bh + 2);
                }
            }
        }
    }
    __syncthreads();   // all reads of sX / sW done before v overlay

    // ---- v staging into dead phase-1 region, overlapped with softmax ----
    for (int L = tid; L < SLIM * 8; L += 256) {
        int s = L >> 3, seg = L & 7;
        CP_ASYNC16(smaddr(&sV[s * 72 + seg * 8]),
                   &g_v[(size_t)(b * NT + s) * 64 + seg * 8]);
    }
    CP_COMMIT;

    // ---- tanh + causal mask + exp + row sums (tanh bounded: no max pass) ----
    const int tg0 = tb * 64 + wm * 16 + qr;
    float rsum0 = 0.f, rsum1 = 0.f;
#pragma unroll
    for (int j = 0; j < NTW; j++) {
        const int c0 = nw0 + j * 8 + qc;
        if (nw0 + j * 8 <= limit) {
            float v0 = (c0     <= tg0    ) ? __expf(tanh_fast(acc[j][0])) : 0.f;
            float v1 = (c0 + 1 <= tg0    ) ? __expf(tanh_fast(acc[j][1])) : 0.f;
            float v2 = (c0     <= tg0 + 8) ? __expf(tanh_fast(acc[j][2])) : 0.f;
            float v3 = (c0 + 1 <= tg0 + 8) ? __expf(tanh_fast(acc[j][3])) : 0.f;
            acc[j][0] = v0; acc[j][1] = v1; acc[j][2] = v2; acc[j][3] = v3;
            rsum0 += v0 + v1;
            rsum1 += v2 + v3;
        }
    }
#pragma unroll
    for (int off = 1; off <= 2; off <<= 1) {
        rsum0 += __shfl_xor_sync(0xffffffffu, rsum0, off);
        rsum1 += __shfl_xor_sync(0xffffffffu, rsum1, off);
    }
    if ((lane & 3) == 0) {
        rowsumS[wn * 64 + wm * 16 + qr]     = rsum0;
        rowsumS[wn * 64 + wm * 16 + qr + 8] = rsum1;
    }
    __syncthreads();
    const float inv0 = 1.f / (rowsumS[wm * 16 + qr]     + rowsumS[64 + wm * 16 + qr]);
    const float inv1 = 1.f / (rowsumS[wm * 16 + qr + 8] + rowsumS[64 + wm * 16 + qr + 8]);

    CP_WAIT0;
    __syncthreads();

    // ---- GEMM2: out += p @ v over k in [wn*KW, wn*KW+KW); p single fp16 ----
    float acc2[8][4];
#pragma unroll
    for (int jo = 0; jo < 8; jo++)
#pragma unroll
        for (int q = 0; q < 4; q++) acc2[jo][q] = 0.f;

#pragma unroll
    for (int jp = 0; jp < NTW / 2; jp++) {
        const int k0 = nw0 + jp * 16;
        if (k0 <= limit) {   // warp-uniform causal k-pair skip
            uint32_t pa_h[4];
            pa_h[0] = pack_h2(acc[2*jp][0]   * inv0, acc[2*jp][1]   * inv0);
            pa_h[1] = pack_h2(acc[2*jp][2]   * inv1, acc[2*jp][3]   * inv1);
            pa_h[2] = pack_h2(acc[2*jp+1][0] * inv0, acc[2*jp+1][1] * inv0);
            pa_h[3] = pack_h2(acc[2*jp+1][2] * inv1, acc[2*jp+1][3] * inv1);

#pragma unroll
            for (int jo = 0; jo < 8; jo += 2) {
                uint32_t bh[4];
                LDSM_X4_T(bh, smaddr(&sV[(k0 + kt_off) * 72 + jo * 8 + nt_off]));
                MMA_F16(acc2[jo],     pa_h, bh);
                MMA_F16(acc2[jo + 1], pa_h, bh + 2);
            }
        }
    }

    // ---- cross-warp k-reduction: both halves store, all threads add+store ----
    __syncthreads();   // v reads done; sOut regions reusable
    {
        float* dst = wn ? sOutB : sOutA;
#pragma unroll
        for (int jo = 0; jo < 8; jo++) {
            *(float2*)&dst[(wm * 16 + qr)     * 72 + jo * 8 + qc] =
                make_float2(acc2[jo][0], acc2[jo][1]);
            *(float2*)&dst[(wm * 16 + qr + 8) * 72 + jo * 8 + qc] =
                make_float2(acc2[jo][2], acc2[jo][3]);
        }
    }
    __syncthreads();
    for (int L = tid; L < 64 * 32; L += 256) {
        int row = L >> 5, c2 = (L & 31) * 2;
        float2 pa = *(float2*)&sOutA[row * 72 + c2];
        float2 pb = *(float2*)&sOutB[row * 72 + c2];
        *(float2*)&out[(size_t)(base_row + row) * NH + c2] =
            make_float2(pa.x + pb.x, pa.y + pb.y);
    }
}

__global__ __launch_bounds__(256, 2) void attn_kernel(float* __restrict__ out)
{
    // heavy-first 1D order: bid 0-511 -> tb=3 (SLIM=256), ..., 1536-2047 -> tb=0
    const int bid = blockIdx.x;
    const int tb  = 3 - (bid >> 9);
    const int b   = bid & 511;
    if (tb == 3)      attn_body<256>(out, b, 3);
    else if (tb == 2) attn_body<192>(out, b, 2);
    else if (tb == 1) attn_body<128>(out, b, 1);
    else              attn_body<64 >(out, b, 0);
}

extern "C" void kernel_launch(void* const* d_in, const int* in_sizes, int n_in,
                              void* d_out, int out_size)
{
    (void)in_sizes; (void)n_in; (void)out_size;
    const float* x   = (const float*)d_in[0];
    const float* Wq  = (const float*)d_in[1];
    const float* Wk  = (const float*)d_in[2];
    const float* Wv  = (const float*)d_in[3];
    const float* Wql = (const float*)d_in[4];
    const float* Wkl = (const float*)d_in[5];
    float* out = (float*)d_out;

    cudaFuncSetAttribute((const void*)attn_kernel,
                         cudaFuncAttributeMaxDynamicSharedMemorySize, ATTN_SMEM_BYTES);
    cudaFuncSetAttribute((const void*)vproj_kernel,
                         cudaFuncAttributeMaxDynamicSharedMemorySize, VPROJ_SMEM);

    prep_kernel<<<144, 256>>>(Wq, Wk, Wql, Wkl, Wv);
    vproj_kernel<<<NM / 256, 256, VPROJ_SMEM>>>(x);

    attn_kernel<<<2048, 256, ATTN_SMEM_BYTES>>>(out);
}

// round 15
// speedup vs baseline: 1.0819x; 1.0819x over previous
#include <cuda_runtime.h>
#include <cuda_fp16.h>
#include <math.h>
#include <stdint.h>

#define NB 512
#define NT 256
#define NC 384
#define NH 64
#define NS 256
#define NM (NB*NT)   // 131072 rows

// scratch (device globals: allocation-guard safe)
__device__ __align__(16) __half g_xh[NM * NC];    // x fp16 [row][384] (written by vproj)
__device__ __align__(16) __half g_v[NM * 64];     // v fp16 [row][64]
__device__ __align__(16) __half g_wv[64 * 384];   // Wv [n][k] K-major fp16
__device__ __align__(16) __half g_wu[384 * 256];  // Wu = Wq@Wql + Wk@Wkl, [k][s] fp16

// ---------------- mma.sync / cp.async helpers (baseline PTX ISA) ----------------
#define LDSM_X4(r, addr)                                                        \
    asm volatile("ldmatrix.sync.aligned.m8n8.x4.shared.b16 {%0,%1,%2,%3}, [%4];" \
        : "=r"((r)[0]), "=r"((r)[1]), "=r"((r)[2]), "=r"((r)[3]) : "r"(addr))

#define LDSM_X4_T(r, addr)                                                      \
    asm volatile("ldmatrix.sync.aligned.m8n8.x4.trans.shared.b16 {%0,%1,%2,%3}, [%4];" \
        : "=r"((r)[0]), "=r"((r)[1]), "=r"((r)[2]), "=r"((r)[3]) : "r"(addr))

#define MMA_F16(d, a, b)                                                        \
    asm volatile("mma.sync.aligned.m16n8k16.row.col.f32.f16.f16.f32 "           \
        "{%0,%1,%2,%3}, {%4,%5,%6,%7}, {%8,%9}, {%0,%1,%2,%3};"                 \
        : "+f"((d)[0]), "+f"((d)[1]), "+f"((d)[2]), "+f"((d)[3])                \
        : "r"((a)[0]), "r"((a)[1]), "r"((a)[2]), "r"((a)[3]),                   \
          "r"((b)[0]), "r"((b)[1]))

#define CP_ASYNC16(dst, src)                                                    \
    asm volatile("cp.async.cg.shared.global [%0], [%1], 16;"                    \
        :: "r"(dst), "l"(src))
#define CP_COMMIT  asm volatile("cp.async.commit_group;" ::: "memory")
#define CP_WAIT0   asm volatile("cp.async.wait_group 0;" ::: "memory")
#define CP_WAIT1   asm volatile("cp.async.wait_group 1;" ::: "memory")

static __device__ __forceinline__ uint32_t pack_h2(float a, float b) {
    __half2 t = __floats2half2_rn(a, b);
    return *(uint32_t*)&t;
}
static __device__ __forceinline__ uint32_t smaddr(const void* p) {
    return (uint32_t)__cvta_generic_to_shared(p);
}
static __device__ __forceinline__ float tanh_fast(float v) {
    float y;
    asm("tanh.approx.f32 %0, %1;" : "=f"(y) : "f"(v));
    return y;
}

// ---------------- prep: Wu = Wq@Wql + Wk@Wkl (1 c/block, batch-32 MLP) + Wv->fp16 ----------------
__global__ __launch_bounds__(256) void prep_kernel(
    const float* __restrict__ Wq, const float* __restrict__ Wk,
    const float* __restrict__ Wql, const float* __restrict__ Wkl,
    const float* __restrict__ Wv)
{
    __shared__ float qr_[64], kr_[64];
    const int bb = blockIdx.x;
    const int s  = threadIdx.x;
    if (bb < 384) {
        const int c = bb;
        if (s < 64)       qr_[s]      = Wq[c * 64 + s];
        else if (s < 128) kr_[s - 64] = Wk[c * 64 + s - 64];
        __syncthreads();
        float acc = 0.f;
#pragma unroll
        for (int hb = 0; hb < 2; hb++) {
            float wql[32], wkl[32];
#pragma unroll
            for (int i = 0; i < 32; i++) {      // 64 independent LDGs in flight
                wql[i] = Wql[(hb * 32 + i) * 256 + s];
                wkl[i] = Wkl[(hb * 32 + i) * 256 + s];
            }
#pragma unroll
            for (int i = 0; i < 32; i++)
                acc = fmaf(qr_[hb * 32 + i], wql[i], fmaf(kr_[hb * 32 + i], wkl[i], acc));
        }
        g_wu[c * 256 + s] = __float2half_rn(acc);
    } else {
        const int idx = (bb - 384) * 256 + s;
        if (idx < 64 * 384) {
            const int n = idx / 384, k = idx % 384;
            g_wv[idx] = __float2half_rn(Wv[k * 64 + n]);
        }
    }
}

// ---------------- Kernel A: v projection + x fp16 export (unchanged) ----------------
#define VPROJ_SMEM ((64*392 + 256*40) * 2)   // 70656 B

__global__ __launch_bounds__(256, 2) void vproj_kernel(const float* __restrict__ x)
{
    extern __shared__ __half smv[];
    __half* sWv = smv;               // [64][392]
    __half* sX  = smv + 64 * 392;    // [256][40]

    const int tid  = threadIdx.x;
    const int lane = tid & 31;
    const int w    = tid >> 5;
    const int wm   = w & 3;
    const int wn   = w >> 2;
    const int m0   = blockIdx.x * 256;

    const int a_row = (lane & 7) + ((lane >> 3) & 1) * 8;
    const int a_col = (lane >> 4) * 8;
    const int b_row = ((lane >> 4) * 8) + (lane & 7);
    const int b_k8  = ((lane >> 3) & 1) * 8;
    const int qr    = lane >> 2;
    const int qc    = (lane & 3) * 2;

    for (int L = tid; L < 3072; L += 256) {
        int n = L / 48, seg = L % 48;
        CP_ASYNC16(smaddr(&sWv[n * 392 + seg * 8]), &g_wv[(size_t)n * NC + seg * 8]);
    }
    CP_COMMIT;

    const int xrow = tid >> 3, xseg = tid & 7;
    float4 vv[8];
    auto ldgX = [&](int c) {
#pragma unroll
        for (int i = 0; i < 8; i++) {
            int row = xrow + 32 * i;
            vv[i] = *(const float4*)&x[(size_t)(m0 + row) * NC + c * 32 + xseg * 4];
        }
    };
    auto cvtX = [&](int c) {
#pragma unroll
        for (int i = 0; i < 8; i++) {
            int row = xrow + 32 * i;
            __half h[4];
            h[0] = __float2half_rn(vv[i].x); h[1] = __float2half_rn(vv[i].y);
            h[2] = __float2half_rn(vv[i].z); h[3] = __float2half_rn(vv[i].w);
            *(uint2*)&sX[row * 40 + xseg * 4] = *(uint2*)h;
            *(uint2*)&g_xh[(size_t)(m0 + row) * NC + c * 32 + xseg * 4] = *(uint2*)h;
        }
    };

    ldgX(0);
    CP_WAIT0;
    cvtX(0);
    __syncthreads();

    float acc[4][4][4];
#pragma unroll
    for (int mi = 0; mi < 4; mi++)
#pragma unroll
        for (int ni = 0; ni < 4; ni++)
#pragma unroll
            for (int q = 0; q < 4; q++) acc[mi][ni][q] = 0.f;

    for (int c = 0; c < 12; c++) {
        if (c < 11) ldgX(c + 1);
#pragma unroll
        for (int kk = 0; kk < 2; kk++) {
            const int kglob = c * 32 + kk * 16;
            uint32_t ah[4][4];
#pragma unroll
            for (int mi = 0; mi < 4; mi++)
                LDSM_X4(ah[mi], smaddr(&sX[(wm * 64 + mi * 16 + a_row) * 40 + kk * 16 + a_col]));
#pragma unroll
            for (int ni = 0; ni < 4; ni += 2) {
                uint32_t bh[4];
                LDSM_X4(bh, smaddr(&sWv[(wn * 32 + ni * 8 + b_row) * 392 + kglob + b_k8]));
#pragma unroll
                for (int mi = 0; mi < 4; mi++) {
                    MMA_F16(acc[mi][ni],     ah[mi], bh);
                    MMA_F16(acc[mi][ni + 1], ah[mi], bh + 2);
                }
            }
        }
        __syncthreads();
        if (c < 11) cvtX(c + 1);
        __syncthreads();
    }

#pragma unroll
    for (int mi = 0; mi < 4; mi++) {
        int r0 = m0 + wm * 64 + mi * 16 + qr;
#pragma unroll
        for (int ni = 0; ni < 4; ni++) {
            int col = wn * 32 + ni * 8 + qc;
            *(uint32_t*)&g_v[(size_t)r0 * 64 + col]       = pack_h2(acc[mi][ni][0], acc[mi][ni][1]);
            *(uint32_t*)&g_v[(size_t)(r0 + 8) * 64 + col] = pack_h2(acc[mi][ni][2], acc[mi][ni][3]);
        }
    }
}

// ---------------- Kernel B: fused u-GEMM + softmax + p@v (x fully smem-resident) ----------------
#define ATTN_SMEM_BYTES 101376

template <int SLIM>
__device__ __forceinline__ void attn_body(float* __restrict__ out, int b, int tb)
{
    constexpr int SLIMP = SLIM + 8;
    constexpr int NTW   = SLIM / 16;
    constexpr int KW    = SLIM / 2;

    extern __shared__ char smraw[];
    // phase 1
    __half* sX  = (__half*)smraw;             // [64][392]   (resident x)
    __half* sWH = sX + 64 * 392;              // [3][32][SLIMP]
    // phase 2 (overlays sX region)
    __half* sV  = (__half*)smraw;             // [SLIM][72]
    float* sOutA   = (float*)smraw;           // [64][72]
    float* sOutB   = sOutA + 64 * 72;
    float* rowsumS = (float*)(smraw + 100864);// [2][64]

    const int tid  = threadIdx.x;
    const int lane = tid & 31;
    const int w    = tid >> 5;
    const int wm   = w >> 1;
    const int wn   = w & 1;

    const int a_row  = (lane & 7) + ((lane >> 3) & 1) * 8;
    const int a_col  = (lane >> 4) * 8;
    const int kt_off = (lane & 7) | (((lane >> 3) & 1) << 3);
    const int nt_off = (lane >> 4) * 8;
    const int qr     = lane >> 2;
    const int qc     = (lane & 3) * 2;
    const int base_row = b * NT + tb * 64;

    const int limit = tb * 64 + wm * 16 + 15;
    const int nw0   = wn * KW;

    auto stageW = [&](int c, int buf) {
        const int kc = c * 32;
        for (int L = tid; L < 4 * SLIM; L += 256) {
            int r = L / (SLIM / 8), cs = L % (SLIM / 8);
            CP_ASYNC16(smaddr(&sWH[(buf * 32 + r) * SLIMP + cs * 8]),
                       &g_wu[(size_t)(kc + r) * 256 + cs * 8]);
        }
    };

    // prologue: resident x (group 0), W stages 0,1 (groups 1,2)
    for (int L = tid; L < 3072; L += 256) {
        int row = L / 48, seg = L % 48;
        CP_ASYNC16(smaddr(&sX[row * 392 + seg * 8]),
                   &g_xh[(size_t)(base_row + row) * NC + seg * 8]);
    }
    CP_COMMIT;
    stageW(0, 0); CP_COMMIT;
    stageW(1, 1); CP_COMMIT;

    // ---- GEMM1: u = x @ Wu, K=384, 12 chunks, 3-stage W pipeline ----
    float acc[NTW][4];
#pragma unroll
    for (int j = 0; j < NTW; j++)
#pragma unroll
        for (int q = 0; q < 4; q++) acc[j][q] = 0.f;

    for (int c = 0; c < 12; c++) {
        if (c == 11) { CP_WAIT0; } else { CP_WAIT1; }
        __syncthreads();
        if (c + 2 < 12) { stageW(c + 2, (c + 2) % 3); CP_COMMIT; }
        const int buf = c % 3;
#pragma unroll
        for (int kk = 0; kk < 2; kk++) {
            uint32_t ah[4];
            LDSM_X4(ah, smaddr(&sX[(wm * 16 + a_row) * 392 + c * 32 + kk * 16 + a_col]));
#pragma unroll
            for (int j = 0; j < NTW; j += 2) {
                const int n0 = nw0 + j * 8;
                if (n0 <= limit) {
                    uint32_t bh[4];
                    LDSM_X4_T(bh, smaddr(&sWH[(buf * 32 + kk * 16 + kt_off) * SLIMP + n0 + nt_off]));
                    MMA_F16(acc[j],     ah, bh);
                    MMA_F16(acc[j + 1], ah, bh + 2);
                }
            }
        }
    }
    __syncthreads();   // all reads of sX / sW done before v overlay

    // ---- v staging into dead phase-1 region, overlapped with softmax ----
    for (int L = tid; L < SLIM * 8; L += 256) {
        int s = L >> 3, seg = L & 7;
        CP_ASYNC16(smaddr(&sV[s * 72 + seg * 8]),
                   &g_v[(size_t)(b * NT + s) * 64 + seg * 8]);
    }
    CP_COMMIT;

    // ---- tanh + causal mask + exp + row sums ----
    const int tg0 = tb * 64 + wm * 16 + qr;
    float rsum0 = 0.f, rsum1 = 0.f;
#pragma unroll
    for (int j = 0; j < NTW; j++) {
        const int c0 = nw0 + j * 8 + qc;
        if (nw0 + j * 8 <= limit) {
            float v0 = (c0     <= tg0    ) ? __expf(tanh_fast(acc[j][0])) : 0.f;
            float v1 = (c0 + 1 <= tg0    ) ? __expf(tanh_fast(acc[j][1])) : 0.f;
            float v2 = (c0     <= tg0 + 8) ? __expf(tanh_fast(acc[j][2])) : 0.f;
            float v3 = (c0 + 1 <= tg0 + 8) ? __expf(tanh_fast(acc[j][3])) : 0.f;
            acc[j][0] = v0; acc[j][1] = v1; acc[j][2] = v2; acc[j][3] = v3;
            rsum0 += v0 + v1;
            rsum1 += v2 + v3;
        }
    }
#pragma unroll
    for (int off = 1; off <= 2; off <<= 1) {
        rsum0 += __shfl_xor_sync(0xffffffffu, rsum0, off);
        rsum1 += __shfl_xor_sync(0xffffffffu, rsum1, off);
    }
    if ((lane & 3) == 0) {
        rowsumS[wn * 64 + wm * 16 + qr]     = rsum0;
        rowsumS[wn * 64 + wm * 16 + qr + 8] = rsum1;
    }
    __syncthreads();
    const float inv0 = 1.f / (rowsumS[wm * 16 + qr]     + rowsumS[64 + wm * 16 + qr]);
    const float inv1 = 1.f / (rowsumS[wm * 16 + qr + 8] + rowsumS[64 + wm * 16 + qr + 8]);

    CP_WAIT0;
    __syncthreads();

    // ---- GEMM2: out += p @ v ----
    float acc2[8][4];
#pragma unroll
    for (int jo = 0; jo < 8; jo++)
#pragma unroll
        for (int q = 0; q < 4; q++) acc2[jo][q] = 0.f;

#pragma unroll
    for (int jp = 0; jp < NTW / 2; jp++) {
        const int k0 = nw0 + jp * 16;
        if (k0 <= limit) {
            uint32_t pa_h[4];
            pa_h[0] = pack_h2(acc[2*jp][0]   * inv0, acc[2*jp][1]   * inv0);
            pa_h[1] = pack_h2(acc[2*jp][2]   * inv1, acc[2*jp][3]   * inv1);
            pa_h[2] = pack_h2(acc[2*jp+1][0] * inv0, acc[2*jp+1][1] * inv0);
            pa_h[3] = pack_h2(acc[2*jp+1][2] * inv1, acc[2*jp+1][3] * inv1);

#pragma unroll
            for (int jo = 0; jo < 8; jo += 2) {
                uint32_t bh[4];
                LDSM_X4_T(bh, smaddr(&sV[(k0 + kt_off) * 72 + jo * 8 + nt_off]));
                MMA_F16(acc2[jo],     pa_h, bh);
                MMA_F16(acc2[jo + 1], pa_h, bh + 2);
            }
        }
    }

    // ---- cross-warp k-reduction: both halves store, all threads add+store ----
    __syncthreads();
    {
        float* dst = wn ? sOutB : sOutA;
#pragma unroll
        for (int jo = 0; jo < 8; jo++) {
            *(float2*)&dst[(wm * 16 + qr)     * 72 + jo * 8 + qc] =
                make_float2(acc2[jo][0], acc2[jo][1]);
            *(float2*)&dst[(wm * 16 + qr + 8) * 72 + jo * 8 + qc] =
                make_float2(acc2[jo][2], acc2[jo][3]);
        }
    }
    __syncthreads();
    for (int L = tid; L < 64 * 32; L += 256) {
        int row = L >> 5, c2 = (L & 31) * 2;
        float2 pa = *(float2*)&sOutA[row * 72 + c2];
        float2 pb = *(float2*)&sOutB[row * 72 + c2];
        *(float2*)&out[(size_t)(base_row + row) * NH + c2] =
            make_float2(pa.x + pb.x, pa.y + pb.y);
    }
}

__global__ __launch_bounds__(256, 2) void attn_kernel(float* __restrict__ out)
{
    const int bid = blockIdx.x;
    const int tb  = 3 - (bid >> 9);
    const int b   = bid & 511;
    if (tb == 3)      attn_body<256>(out, b, 3);
    else if (tb == 2) attn_body<192>(out, b, 2);
    else if (tb == 1) attn_body<128>(out, b, 1);
    else              attn_body<64 >(out, b, 0);
}

extern "C" void kernel_launch(void* const* d_in, const int* in_sizes, int n_in,
                              void* d_out, int out_size)
{
    (void)in_sizes; (void)n_in; (void)out_size;
    const float* x   = (const float*)d_in[0];
    const float* Wq  = (const float*)d_in[1];
    const float* Wk  = (const float*)d_in[2];
    const float* Wv  = (const float*)d_in[3];
    const float* Wql = (const float*)d_in[4];
    const float* Wkl = (const float*)d_in[5];
    float* out = (float*)d_out;

    cudaFuncSetAttribute((const void*)attn_kernel,
                         cudaFuncAttributeMaxDynamicSharedMemorySize, ATTN_SMEM_BYTES);
    cudaFuncSetAttribute((const void*)vproj_kernel,
                         cudaFuncAttributeMaxDynamicSharedMemorySize, VPROJ_SMEM);

    prep_kernel<<<480, 256>>>(Wq, Wk, Wql, Wkl, Wv);
    vproj_kernel<<<NM / 256, 256, VPROJ_SMEM>>>(x);

    attn_kernel<<<2048, 256, ATTN_SMEM_BYTES>>>(out);
}